// round 2
// baseline (speedup 1.0000x reference)
#include <cuda_runtime.h>
#include <cuda_bf16.h>

#define EPS_F      1e-07f
#define FN_PENALTY 10.0f
#define W_CLASS 1.0f
#define W_BBOX  5.0f
#define W_GIOU  2.0f
#define W_CUT   3.0f

// -------- device scratch (no allocations allowed) --------
__device__ double g_acc[4];   // focal, bbox, giou, bce sums
__device__ int    g_lab64;    // 1 if labels are int64, 0 if int32
__device__ unsigned int g_done;  // block completion counter

// ---------------------------------------------------------------
// Kernel 0: zero accumulators + detect label dtype (parallel).
// int64 labels (values 0..3, little-endian): every odd 32-bit word
// is 0. int32 labels: those words are random labels in [0,4).
// P(256 random words all zero) = 4^-256 ~ 0.
// ---------------------------------------------------------------
__global__ void init_detect_kernel(const int* __restrict__ labels_w, int n)
{
    __shared__ int nonzero;
    if (threadIdx.x == 0) {
        nonzero = 0;
        g_acc[0] = 0.0; g_acc[1] = 0.0; g_acc[2] = 0.0; g_acc[3] = 0.0;
        g_done = 0u;
    }
    __syncthreads();
    int nchk = (n / 2 < 256) ? n / 2 : 256;   // safe to read word 2i+1 in both layouts
    int i = threadIdx.x;
    if (i < nchk && labels_w[2 * i + 1] != 0) atomicOr(&nonzero, 1);
    __syncthreads();
    if (threadIdx.x == 0) g_lab64 = (nonzero == 0) ? 1 : 0;
}

// validate_and_fix from the reference
__device__ __forceinline__ float4 fix_box(float4 b)
{
    bool invalid = (b.x > b.z) || (b.y > b.w);
    if (invalid) {
        b.x = fmaxf(b.x, 0.0f); b.y = fmaxf(b.y, 0.0f);
        b.z = fmaxf(b.z, 0.0f); b.w = fmaxf(b.w, 0.0f);
    }
    b.z = fmaxf(b.z, b.x + 1e-6f);
    b.w = fmaxf(b.w, b.y + 1e-6f);
    return b;
}

// per-element losses, accumulated into s[4]
__device__ __forceinline__ void accum_elem(float4 L, int t, float4 pb, float4 tb,
                                           float cl, float ct,
                                           float& s_focal, float& s_bbox,
                                           float& s_giou, float& s_bce)
{
    // focal (4-class softmax CE)
    float m  = fmaxf(fmaxf(L.x, L.y), fmaxf(L.z, L.w));
    float s  = __expf(L.x - m) + __expf(L.y - m)
             + __expf(L.z - m) + __expf(L.w - m);
    float lt = (t == 0) ? L.x : (t == 1) ? L.y : (t == 2) ? L.z : L.w;
    float ce = __logf(s) - (lt - m);
    float pt = __expf(-ce);
    float omp = 1.0f - pt;
    s_focal += omp * omp * ce;

    // bbox L1
    s_bbox += fabsf(pb.x - tb.x) + fabsf(pb.y - tb.y)
            + fabsf(pb.z - tb.z) + fabsf(pb.w - tb.w);

    // GIoU
    float4 b1 = fix_box(pb);
    float4 b2 = fix_box(tb);
    float area1 = (b1.z - b1.x) * (b1.w - b1.y);
    float area2 = (b2.z - b2.x) * (b2.w - b2.y);
    float iw = fmaxf(fminf(b1.z, b2.z) - fmaxf(b1.x, b2.x), 0.0f);
    float ih = fmaxf(fminf(b1.w, b2.w) - fmaxf(b1.y, b2.y), 0.0f);
    float inter = iw * ih;
    float uni   = area1 + area2 - inter;
    float iou   = inter / (uni + EPS_F);
    float ew = fmaxf(fmaxf(b1.z, b2.z) - fminf(b1.x, b2.x), 0.0f);
    float eh = fmaxf(fmaxf(b1.w, b2.w) - fminf(b1.y, b2.y), 0.0f);
    float enc = ew * eh;
    float giou = iou - (enc - uni) / (enc + EPS_F);
    s_giou += fmaxf(1.0f - giou, 0.0f);

    // weighted BCE  (sigmoid(cl) < 0.5  <=>  cl < 0)
    float bce = fmaxf(cl, 0.0f) - cl * ct + log1pf(__expf(-fabsf(cl)));
    float w = ((ct == 1.0f) && (cl < 0.0f)) ? FN_PENALTY : 1.0f;
    s_bce += bce * w;
}

// ---------------------------------------------------------------
// Kernel 1: fused losses + reduction + last-block finalize.
// Each block iteration covers a tile of blockDim*4 = 1024 elements,
// 4 elements per thread, coalesced (element = tile + tid + k*256).
// ---------------------------------------------------------------
__global__ void __launch_bounds__(256)
fused_loss_kernel(const float4* __restrict__ logits,
                  const int*    __restrict__ labels_w,
                  const float4* __restrict__ pboxes,
                  const float4* __restrict__ tboxes,
                  const float4* __restrict__ cut_logits4,
                  const float4* __restrict__ cut_targets4,
                  float* __restrict__ out,
                  int n)
{
    const int lab64 = g_lab64;
    float s_focal = 0.0f, s_bbox = 0.0f, s_giou = 0.0f, s_bce = 0.0f;

    const int tile_sz   = blockDim.x * 4;              // 1024
    const long tile_str = (long)gridDim.x * tile_sz;

    for (long tile = (long)blockIdx.x * tile_sz; tile < n; tile += tile_str) {
        long e0 = tile + threadIdx.x;                  // k = 0..3: e0 + k*256
        if (tile + tile_sz <= n) {
            // full tile: all 4 elements valid, vector loads for cut arrays
            // cut vector index: elements e0+k*256 -> pattern not contiguous per
            // thread, so load per-k from scalar view via float4 at (tile/4 ...)
            #pragma unroll
            for (int k = 0; k < 4; ++k) {
                long e = e0 + k * 256;
                float4 L  = __ldg(&logits[e]);
                int t;
                if (lab64) { t = __ldg(&labels_w[2 * e]); }
                else       { t = __ldg(&labels_w[e]); }
                float4 pb = __ldg(&pboxes[e]);
                float4 tb = __ldg(&tboxes[e]);
                float cl  = __ldg(((const float*)cut_logits4)  + e);
                float ct  = __ldg(((const float*)cut_targets4) + e);
                accum_elem(L, t, pb, tb, cl, ct, s_focal, s_bbox, s_giou, s_bce);
            }
        } else {
            #pragma unroll
            for (int k = 0; k < 4; ++k) {
                long e = e0 + k * 256;
                if (e < n) {
                    float4 L  = __ldg(&logits[e]);
                    int t = lab64 ? __ldg(&labels_w[2 * e]) : __ldg(&labels_w[e]);
                    float4 pb = __ldg(&pboxes[e]);
                    float4 tb = __ldg(&tboxes[e]);
                    float cl  = __ldg(((const float*)cut_logits4)  + e);
                    float ct  = __ldg(((const float*)cut_targets4) + e);
                    accum_elem(L, t, pb, tb, cl, ct, s_focal, s_bbox, s_giou, s_bce);
                }
            }
        }
    }

    // -------- warp reduce --------
    #pragma unroll
    for (int off = 16; off > 0; off >>= 1) {
        s_focal += __shfl_down_sync(0xffffffffu, s_focal, off);
        s_bbox  += __shfl_down_sync(0xffffffffu, s_bbox,  off);
        s_giou  += __shfl_down_sync(0xffffffffu, s_giou,  off);
        s_bce   += __shfl_down_sync(0xffffffffu, s_bce,   off);
    }

    __shared__ float sh[4][8];
    int lane = threadIdx.x & 31;
    int wid  = threadIdx.x >> 5;
    if (lane == 0) {
        sh[0][wid] = s_focal; sh[1][wid] = s_bbox;
        sh[2][wid] = s_giou;  sh[3][wid] = s_bce;
    }
    __syncthreads();

    __shared__ bool is_last;
    if (threadIdx.x == 0) {
        float v0 = 0.f, v1 = 0.f, v2 = 0.f, v3 = 0.f;
        #pragma unroll
        for (int w = 0; w < 8; ++w) {
            v0 += sh[0][w]; v1 += sh[1][w]; v2 += sh[2][w]; v3 += sh[3][w];
        }
        atomicAdd(&g_acc[0], (double)v0);
        atomicAdd(&g_acc[1], (double)v1);
        atomicAdd(&g_acc[2], (double)v2);
        atomicAdd(&g_acc[3], (double)v3);
        __threadfence();
        unsigned int prev = atomicAdd(&g_done, 1u);
        is_last = (prev == gridDim.x - 1u);
    }
    __syncthreads();

    // -------- last block finalizes output --------
    if (is_last && threadIdx.x == 0) {
        double inv_n = 1.0 / (double)n;
        float lc = fmaxf((float)(g_acc[0] * inv_n), 0.0f);
        float lb = fmaxf((float)(g_acc[1] * inv_n * 0.25), 0.0f);
        float lg = fmaxf((float)(g_acc[2] * inv_n), 0.0f);
        float lu = fmaxf((float)(g_acc[3] * inv_n), 0.0f);
        out[0] = W_CLASS * lc + W_BBOX * lb + W_GIOU * lg + W_CUT * lu;
        out[1] = lc;
        out[2] = lb;
        out[3] = lg;
        out[4] = lu;
    }
}

// ---------------------------------------------------------------
// Inputs (metadata order):
//   0 pred_logits    float32 [N,4]
//   1 target_labels  int64/int32 [N]
//   2 pred_boxes     float32 [N,4]
//   3 target_boxes   float32 [N,4]
//   4 cutting_logits float32 [N]
//   5 cutting_targets float32 [N]
// output: 5 x float32
// ---------------------------------------------------------------
extern "C" void kernel_launch(void* const* d_in, const int* in_sizes, int n_in,
                              void* d_out, int out_size)
{
    const float4* logits   = (const float4*)d_in[0];
    const int*    labels_w = (const int*)   d_in[1];
    const float4* pboxes   = (const float4*)d_in[2];
    const float4* tboxes   = (const float4*)d_in[3];
    const float4* cl       = (const float4*)d_in[4];
    const float4* ct       = (const float4*)d_in[5];
    float*        out      = (float*)d_out;

    const int n = in_sizes[1];   // N

    init_detect_kernel<<<1, 256>>>(labels_w, n);

    const int threads = 256;
    const int tile = threads * 4;
    int blocks_needed = (n + tile - 1) / tile;
    int blocks = 148 * 8;                 // one full wave @ 256 thr, 8 blk/SM
    if (blocks > blocks_needed) blocks = blocks_needed;

    fused_loss_kernel<<<blocks, threads>>>(logits, labels_w, pboxes, tboxes,
                                           cl, ct, out, n);
}